// round 2
// baseline (speedup 1.0000x reference)
#include <cuda_runtime.h>
#include <cuda_bf16.h>

// ---------------------------------------------------------------------------
// DIN forward, fp32, f32x2-packed FMA.
// Kernel 1: per-batch-row attention -> g_interest[B][64]
// Kernel 2: batched final MLP (32 rows per CTA) -> d_out[B]
// ---------------------------------------------------------------------------

#define B_ROWS 4096
#define T_LEN  200
#define TP     224          // padded T (16 warps * 14)
#define E_DIM  64

__device__ float g_interest[B_ROWS * E_DIM];

__device__ __forceinline__ float2 fma2(float2 a, float2 b, float2 c) {
    float2 d;
    asm("fma.rn.f32x2 %0, %1, %2, %3;"
        : "=l"(*(unsigned long long*)&d)
        : "l"(*(unsigned long long*)&a),
          "l"(*(unsigned long long*)&b),
          "l"(*(unsigned long long*)&c));
    return d;
}

// ---- smem layout (floats) for kernel 1 ----
#define OFF_XT   0                 // 64 x 224            = 14336
#define OFF_W12  14336             // 4096 float2 (dup)   = 8192 floats
#define OFF_H1   22528             // 64 x 226            = 14464
#define OFF_W2D  36992             // 2048 float2 (dup)   = 4096 floats
#define OFF_Q    41088             // 64
#define OFF_QC   41152             // 64
#define OFF_SC   41216             // 224
#define OFF_WG   41440             // 224
#define OFF_RED  41664             // 32
#define OFF_SV   41696             // 2
#define OFF_MSK  41698             // 224 bytes (uchar), occupies 56 floats
#define SMEM1_BYTES (167040)

__global__ void __launch_bounds__(512, 1)
din_attn_kernel(const int* __restrict__ tgt,
                const int* __restrict__ hist,
                const int* __restrict__ mask,          // bool shipped as int32
                const float* __restrict__ item_table,
                const float* __restrict__ w1, const float* __restrict__ b1,
                const float* __restrict__ w2, const float* __restrict__ b2,
                const float* __restrict__ wo, const float* __restrict__ bo)
{
    extern __shared__ float sm[];
    float*  XT  = sm + OFF_XT;
    float2* W12 = (float2*)(sm + OFF_W12);
    float*  H1  = sm + OFF_H1;
    float2* W2D = (float2*)(sm + OFF_W2D);
    float*  Q   = sm + OFF_Q;
    float*  QC  = sm + OFF_QC;
    float*  SC  = sm + OFF_SC;
    float*  WG  = sm + OFF_WG;
    float*  RED = sm + OFF_RED;
    float*  SV  = sm + OFF_SV;
    unsigned char* MSK = (unsigned char*)(sm + OFF_MSK);

    const int b    = blockIdx.x;
    const int tid  = threadIdx.x;
    const int lane = tid & 31;
    const int warp = tid >> 5;

    // ---- phase 0: load q, mask, W2 (duplicated), gather keys transposed ----
    if (tid < E_DIM) Q[tid] = item_table[(long)tgt[b] * E_DIM + tid];
    if (tid < TP)    MSK[tid] = (tid < T_LEN) ? (unsigned char)(mask[b * T_LEN + tid] != 0)
                                              : (unsigned char)0;

    for (int i = tid; i < 64 * 32; i += 512) {
        float v = w2[i];
        W2D[i] = make_float2(v, v);
    }

    // keys: XT[e][t] (stride TP). Lanes walk consecutive t -> conflict-free STS.
    for (int i = tid; i < 16 * TP; i += 512) {
        int t = i % TP;
        int f = i / TP;      // float4 chunk of the embedding (0..15)
        float4 v = make_float4(0.f, 0.f, 0.f, 0.f);
        if (t < T_LEN) {
            int row = hist[b * T_LEN + t];
            v = *(const float4*)(item_table + (long)row * E_DIM + 4 * f);
        }
        XT[(4 * f + 0) * TP + t] = v.x;
        XT[(4 * f + 1) * TP + t] = v.y;
        XT[(4 * f + 2) * TP + t] = v.z;
        XT[(4 * f + 3) * TP + t] = v.w;
    }
    __syncthreads();

    // ---- phase 1: fold weights.  W12[k][j] = (Wk+Wd)[k][j] + q[k]*Wp[k][j]
    //      qc[j] = b1[j] + sum_e q[e]*(Wq-Wd)[e][j]
    for (int i = tid; i < 4096; i += 512) {
        int k = i >> 6;
        float v = w1[i] + w1[8192 + i] + Q[k] * w1[12288 + i];
        W12[i] = make_float2(v, v);
    }
    if (tid < E_DIM) {
        float s = b1[tid];
        #pragma unroll 8
        for (int e = 0; e < 64; ++e)
            s += Q[e] * (w1[4096 + e * 64 + tid] - w1[8192 + e * 64 + tid]);
        QC[tid] = s;
    }
    __syncthreads();

    // ---- phase 2: GEMM1  h1[m][j] = relu( sum_k XT[k][m]*W12[k][j] + qc[j] )
    // warp owns m in [14w, 14w+14), lane owns columns {lane, lane+32}
    const int mb = warp * 14;
    float2 acc0[7], acc1[7];
    #pragma unroll
    for (int p = 0; p < 7; ++p) { acc0[p] = make_float2(0.f, 0.f); acc1[p] = make_float2(0.f, 0.f); }

    #pragma unroll 4
    for (int k = 0; k < 64; ++k) {
        float2 bb0 = W12[k * 64 + lane];
        float2 bb1 = W12[k * 64 + lane + 32];
        const float* xr = XT + k * TP + mb;
        #pragma unroll
        for (int p = 0; p < 7; ++p) {
            float2 a = *(const float2*)(xr + 2 * p);
            acc0[p] = fma2(a, bb0, acc0[p]);
            acc1[p] = fma2(a, bb1, acc1[p]);
        }
    }
    {
        float qa = QC[lane], qb = QC[lane + 32];
        #pragma unroll
        for (int p = 0; p < 7; ++p) {
            float2 r0 = make_float2(fmaxf(acc0[p].x + qa, 0.f), fmaxf(acc0[p].y + qa, 0.f));
            float2 r1 = make_float2(fmaxf(acc1[p].x + qb, 0.f), fmaxf(acc1[p].y + qb, 0.f));
            *(float2*)(H1 + lane * 226 + mb + 2 * p)        = r0;
            *(float2*)(H1 + (lane + 32) * 226 + mb + 2 * p) = r1;
        }
    }
    __syncthreads();

    // ---- phase 3: GEMM2 (64->32) + score reduction ----
    float2 acc[7];
    #pragma unroll
    for (int p = 0; p < 7; ++p) acc[p] = make_float2(0.f, 0.f);

    #pragma unroll 4
    for (int k = 0; k < 64; ++k) {
        float2 bb = W2D[k * 32 + lane];
        const float* hr = H1 + k * 226 + mb;
        #pragma unroll
        for (int p = 0; p < 7; ++p) {
            float2 a = *(const float2*)(hr + 2 * p);
            acc[p] = fma2(a, bb, acc[p]);
        }
    }
    {
        float bb2 = b2[lane];
        float wol = wo[lane];
        float bos = bo[0];
        #pragma unroll
        for (int p = 0; p < 7; ++p) {
            float hx = fmaxf(acc[p].x + bb2, 0.f) * wol;
            float hy = fmaxf(acc[p].y + bb2, 0.f) * wol;
            #pragma unroll
            for (int off = 16; off > 0; off >>= 1) {
                hx += __shfl_xor_sync(0xffffffffu, hx, off);
                hy += __shfl_xor_sync(0xffffffffu, hy, off);
            }
            if (lane == 0) {
                int m = mb + 2 * p;
                SC[m]     = MSK[m]     ? hx + bos : -1e9f;
                SC[m + 1] = MSK[m + 1] ? hy + bos : -1e9f;
            }
        }
    }
    __syncthreads();

    // ---- phase 4: softmax over 224 (pads carry -1e9 -> weight 0) ----
    {
        float s = (tid < TP) ? SC[tid] : -3.4e38f;
        #pragma unroll
        for (int off = 16; off > 0; off >>= 1)
            s = fmaxf(s, __shfl_xor_sync(0xffffffffu, s, off));
        if (lane == 0) RED[warp] = s;
    }
    __syncthreads();
    if (warp == 0) {
        float m = (lane < 16) ? RED[lane] : -3.4e38f;
        #pragma unroll
        for (int off = 8; off > 0; off >>= 1)
            m = fmaxf(m, __shfl_xor_sync(0xffffffffu, m, off));
        if (lane == 0) SV[0] = m;
    }
    __syncthreads();
    {
        float smax = SV[0];
        float e = 0.f;
        if (tid < TP) {
            e = expf(SC[tid] - smax);
            WG[tid] = e;
        }
        #pragma unroll
        for (int off = 16; off > 0; off >>= 1)
            e += __shfl_xor_sync(0xffffffffu, e, off);
        if (lane == 0) RED[warp] = e;
    }
    __syncthreads();
    if (warp == 0) {
        float t2 = (lane < 16) ? RED[lane] : 0.f;
        #pragma unroll
        for (int off = 8; off > 0; off >>= 1)
            t2 += __shfl_xor_sync(0xffffffffu, t2, off);
        if (lane == 0) SV[1] = t2;
    }
    __syncthreads();

    // ---- phase 5: interest[e] = sum_t wgt[t]*k_t[e] / ssum ----
    // warp w owns e in [4w, 4w+4); lanes walk distinct t (conflict-free)
    {
        const int e0 = warp * 4;
        float s0 = 0.f, s1 = 0.f, s2 = 0.f, s3 = 0.f;
        #pragma unroll
        for (int i = 0; i < 7; ++i) {
            int t = lane + 32 * i;
            float wv = WG[t];
            s0 += wv * XT[(e0 + 0) * TP + t];
            s1 += wv * XT[(e0 + 1) * TP + t];
            s2 += wv * XT[(e0 + 2) * TP + t];
            s3 += wv * XT[(e0 + 3) * TP + t];
        }
        #pragma unroll
        for (int off = 16; off > 0; off >>= 1) {
            s0 += __shfl_xor_sync(0xffffffffu, s0, off);
            s1 += __shfl_xor_sync(0xffffffffu, s1, off);
            s2 += __shfl_xor_sync(0xffffffffu, s2, off);
            s3 += __shfl_xor_sync(0xffffffffu, s3, off);
        }
        if (lane == 0) {
            float invs = 1.0f / SV[1];
            float* gi = g_interest + (long)b * E_DIM + e0;
            gi[0] = s0 * invs;
            gi[1] = s1 * invs;
            gi[2] = s2 * invs;
            gi[3] = s3 * invs;
        }
    }
}

// ---------------------------------------------------------------------------
// Kernel 2: final MLP, 32 batch rows per CTA, 256 threads.
// feat[272] = [user(64), ctx(64), q(64), interest(64), dense(16)]
// ---------------------------------------------------------------------------
#define BTILE 32
#define SMEM2_BYTES (17536 * 4)

__global__ void __launch_bounds__(256, 1)
din_mlp_kernel(const int* __restrict__ tgt,
               const int* __restrict__ sf,
               const float* __restrict__ dense,
               const float* __restrict__ item_table,
               const float* __restrict__ user_table,
               const float* __restrict__ ctx_table,
               const float* __restrict__ w1, const float* __restrict__ b1,
               const float* __restrict__ w2, const float* __restrict__ b2,
               const float* __restrict__ ow, const float* __restrict__ ob,
               float* __restrict__ out)
{
    extern __shared__ float sm[];
    float* At  = sm;            // [272][32]
    float* H1t = sm + 8704;     // [256][34]
    float* R   = sm + 17408;    // [4][32]

    const int b0   = blockIdx.x * BTILE;
    const int tid  = threadIdx.x;
    const int lane = tid & 31;
    const int warp = tid >> 5;

    // build transposed feature tile At[k][b]
    for (int i = tid; i < 272 * BTILE; i += 256) {
        int bb = i & 31;
        int k  = i >> 5;
        int gb = b0 + bb;
        float v;
        if (k < 64)        v = user_table[(long)sf[gb * 2] * 64 + k];
        else if (k < 128)  v = ctx_table[(long)sf[gb * 2 + 1] * 64 + (k - 64)];
        else if (k < 192)  v = item_table[(long)tgt[gb] * 64 + (k - 128)];
        else if (k < 256)  v = g_interest[(long)gb * 64 + (k - 192)];
        else               v = dense[gb * 16 + (k - 256)];
        At[k * 32 + bb] = v;
    }
    __syncthreads();

    // layer 1: 272 -> 256, thread owns output channel n=tid, all 32 b packed
    {
        float2 acc[16];
        #pragma unroll
        for (int p = 0; p < 16; ++p) acc[p] = make_float2(0.f, 0.f);
        #pragma unroll 4
        for (int k = 0; k < 272; ++k) {
            float wv = w1[k * 256 + tid];
            float2 bb = make_float2(wv, wv);
            const float* ar = At + k * 32;
            #pragma unroll
            for (int p = 0; p < 16; ++p)
                acc[p] = fma2(*(const float2*)(ar + 2 * p), bb, acc[p]);
        }
        float bias = b1[tid];
        #pragma unroll
        for (int p = 0; p < 16; ++p) {
            float2 r = make_float2(fmaxf(acc[p].x + bias, 0.f), fmaxf(acc[p].y + bias, 0.f));
            *(float2*)(H1t + tid * 34 + 2 * p) = r;
        }
    }
    __syncthreads();

    // layer 2: 256 -> 128, then dot with out_w, reduce over channels
    if (tid < 128) {
        float2 acc[16];
        #pragma unroll
        for (int p = 0; p < 16; ++p) acc[p] = make_float2(0.f, 0.f);
        #pragma unroll 4
        for (int k = 0; k < 256; ++k) {
            float wv = w2[k * 128 + tid];
            float2 bb = make_float2(wv, wv);
            const float* hr = H1t + k * 34;
            #pragma unroll
            for (int p = 0; p < 16; ++p)
                acc[p] = fma2(*(const float2*)(hr + 2 * p), bb, acc[p]);
        }
        float bias = b2[tid];
        float owl  = ow[tid];
        #pragma unroll
        for (int p = 0; p < 16; ++p) {
            float hx = fmaxf(acc[p].x + bias, 0.f) * owl;
            float hy = fmaxf(acc[p].y + bias, 0.f) * owl;
            #pragma unroll
            for (int off = 16; off > 0; off >>= 1) {
                hx += __shfl_xor_sync(0xffffffffu, hx, off);
                hy += __shfl_xor_sync(0xffffffffu, hy, off);
            }
            if (lane == 0) {
                R[warp * 32 + 2 * p]     = hx;
                R[warp * 32 + 2 * p + 1] = hy;
            }
        }
    }
    __syncthreads();
    if (tid < 32) {
        float s = R[tid] + R[32 + tid] + R[64 + tid] + R[96 + tid] + ob[0];
        out[b0 + tid] = s;
    }
}

// ---------------------------------------------------------------------------
extern "C" void kernel_launch(void* const* d_in, const int* in_sizes, int n_in,
                              void* d_out, int out_size)
{
    const int*           tgt   = (const int*)d_in[0];
    const int*           hist  = (const int*)d_in[1];
    const int*           mask  = (const int*)d_in[2];   // bool -> int32
    const int*           sf    = (const int*)d_in[3];
    const float*         dense = (const float*)d_in[4];
    const float*         item_table = (const float*)d_in[5];
    const float*         user_table = (const float*)d_in[6];
    const float*         ctx_table  = (const float*)d_in[7];
    const float*         att_w1 = (const float*)d_in[8];
    const float*         att_b1 = (const float*)d_in[9];
    const float*         att_w2 = (const float*)d_in[10];
    const float*         att_b2 = (const float*)d_in[11];
    const float*         att_wo = (const float*)d_in[12];
    const float*         att_bo = (const float*)d_in[13];
    const float*         mlp_w1 = (const float*)d_in[14];
    const float*         mlp_b1 = (const float*)d_in[15];
    const float*         mlp_w2 = (const float*)d_in[16];
    const float*         mlp_b2 = (const float*)d_in[17];
    const float*         out_w  = (const float*)d_in[18];
    const float*         out_b  = (const float*)d_in[19];
    float*               out    = (float*)d_out;

    cudaFuncSetAttribute(din_attn_kernel, cudaFuncAttributeMaxDynamicSharedMemorySize, SMEM1_BYTES);
    cudaFuncSetAttribute(din_mlp_kernel,  cudaFuncAttributeMaxDynamicSharedMemorySize, SMEM2_BYTES);

    din_attn_kernel<<<B_ROWS, 512, SMEM1_BYTES>>>(
        tgt, hist, mask, item_table,
        att_w1, att_b1, att_w2, att_b2, att_wo, att_bo);

    din_mlp_kernel<<<B_ROWS / BTILE, 256, SMEM2_BYTES>>>(
        tgt, sf, dense, item_table, user_table, ctx_table,
        mlp_w1, mlp_b1, mlp_w2, mlp_b2, out_w, out_b, out);
}